// round 12
// baseline (speedup 1.0000x reference)
#include <cuda_runtime.h>
#include <cuda_bf16.h>
#include <math.h>

#define N_NODES   100000
#define N_EDGES   800000
#define NODE_IN   32
#define EDGE_DIM  84
#define HIDDEN    24
#define HEAD_HIDDEN 20
#define DEPTH     2
#define LN_EPS    1e-5f

#define WPE 88            // padded weight row (84 -> 88) so LDS.128 is 16B aligned for all k
#define TE 256            // edges per block
#define ETHREADS 256
#define ES_S (TE + 1)     // 257: stride ≡ 1 mod 32 -> conflict-free fill/drain and compute
#define NCH 7             // 84 / 12
#define CW 12

typedef unsigned long long ull;

// ---------------- packed f32x2 helpers (Blackwell FFMA2) ----------------
__device__ __forceinline__ ull pk(float lo, float hi) {
    ull r; asm("mov.b64 %0, {%1,%2};" : "=l"(r) : "f"(lo), "f"(hi)); return r;
}
__device__ __forceinline__ void upk(ull v, float& lo, float& hi) {
    asm("mov.b64 {%0,%1}, %2;" : "=f"(lo), "=f"(hi) : "l"(v));
}
__device__ __forceinline__ ull fma2(ull a, ull b, ull c) {
    ull d; asm("fma.rn.f32x2 %0, %1, %2, %3;" : "=l"(d) : "l"(a), "l"(b), "l"(c)); return d;
}
__device__ __forceinline__ float gelu(float x) {
    return 0.5f * x * (1.0f + erff(x * 0.7071067811865476f));
}

// ---------------- scratch (device globals: allocation-free) ----------------
__device__ float g_h[N_NODES * HIDDEN];
__device__ float g_intr[N_NODES];
__device__ float g_cnt[N_NODES];
__device__ float g_Ps[N_NODES * EDGE_DIM];
__device__ float g_Pd[N_NODES * EDGE_DIM];
__device__ float g_Qs[N_NODES * HIDDEN];
__device__ float g_Qd[N_NODES * HIDDEN];
__device__ float g_agg[N_NODES * HIDDEN];
__device__ float g_e[(size_t)N_EDGES * EDGE_DIM];

// ---------------- small utility kernels ----------------
__global__ void k_zero_cnt() {
    int i = blockIdx.x * blockDim.x + threadIdx.x;
    if (i < N_NODES) g_cnt[i] = 0.0f;
}
__global__ void k_zero_agg() {
    int i = blockIdx.x * blockDim.x + threadIdx.x;
    if (i < N_NODES * HIDDEN) g_agg[i] = 0.0f;
}
__global__ void k_count(const int* __restrict__ dst) {
    int e = blockIdx.x * blockDim.x + threadIdx.x;
    if (e < N_EDGES) atomicAdd(&g_cnt[dst[e]], 1.0f);
}

// ---------------- input projection + intrinsic head ----------------
__global__ void __launch_bounds__(256) k_input(
    const float* __restrict__ x, const float* __restrict__ node_w,
    const float* __restrict__ node_b, const float* __restrict__ ih_w1,
    const float* __restrict__ ih_b1, const float* __restrict__ ih_w2,
    const float* __restrict__ ih_b2)
{
    __shared__ float sw[NODE_IN * HIDDEN];
    __shared__ float sbias[HIDDEN];
    __shared__ float sw1[HIDDEN * HEAD_HIDDEN];
    __shared__ float sb1h[HEAD_HIDDEN];
    __shared__ float sw2[HEAD_HIDDEN];
    __shared__ float sb2h;
    int tid = threadIdx.x;
    for (int i = tid; i < NODE_IN * HIDDEN; i += 256) sw[i] = node_w[i];
    for (int i = tid; i < HIDDEN * HEAD_HIDDEN; i += 256) sw1[i] = ih_w1[i];
    if (tid < HIDDEN) sbias[tid] = node_b[tid];
    if (tid < HEAD_HIDDEN) { sb1h[tid] = ih_b1[tid]; sw2[tid] = ih_w2[tid]; }
    if (tid == 0) sb2h = ih_b2[0];
    __syncthreads();
    int n = blockIdx.x * 256 + tid;
    if (n >= N_NODES) return;

    float xr[NODE_IN];
    #pragma unroll
    for (int k = 0; k < NODE_IN; k += 4) {
        float4 v = *(const float4*)(x + (size_t)n * NODE_IN + k);
        xr[k] = v.x; xr[k+1] = v.y; xr[k+2] = v.z; xr[k+3] = v.w;
    }
    ull acc[HIDDEN / 2];
    #pragma unroll
    for (int j = 0; j < HIDDEN / 2; j++) acc[j] = pk(sbias[2*j], sbias[2*j+1]);
    #pragma unroll 4
    for (int k = 0; k < NODE_IN; k++) {
        ull xv = pk(xr[k], xr[k]);
        const ulonglong2* wr = (const ulonglong2*)(sw + k * HIDDEN);
        ulonglong2 w0 = wr[0], w1 = wr[1], w2 = wr[2], w3 = wr[3], w4 = wr[4], w5 = wr[5];
        acc[0]=fma2(xv,w0.x,acc[0]);  acc[1]=fma2(xv,w0.y,acc[1]);
        acc[2]=fma2(xv,w1.x,acc[2]);  acc[3]=fma2(xv,w1.y,acc[3]);
        acc[4]=fma2(xv,w2.x,acc[4]);  acc[5]=fma2(xv,w2.y,acc[5]);
        acc[6]=fma2(xv,w3.x,acc[6]);  acc[7]=fma2(xv,w3.y,acc[7]);
        acc[8]=fma2(xv,w4.x,acc[8]);  acc[9]=fma2(xv,w4.y,acc[9]);
        acc[10]=fma2(xv,w5.x,acc[10]); acc[11]=fma2(xv,w5.y,acc[11]);
    }
    float h[HIDDEN];
    #pragma unroll
    for (int j = 0; j < HIDDEN / 2; j++) upk(acc[j], h[2*j], h[2*j+1]);
    #pragma unroll
    for (int k = 0; k < HIDDEN; k += 4)
        *(float4*)(g_h + (size_t)n * HIDDEN + k) = make_float4(h[k], h[k+1], h[k+2], h[k+3]);

    // intrinsic head
    ull t[HEAD_HIDDEN / 2];
    #pragma unroll
    for (int j = 0; j < HEAD_HIDDEN / 2; j++) t[j] = pk(sb1h[2*j], sb1h[2*j+1]);
    #pragma unroll 4
    for (int k = 0; k < HIDDEN; k++) {
        ull hv = pk(h[k], h[k]);
        const ull* wr = (const ull*)(sw1 + k * HEAD_HIDDEN);
        #pragma unroll
        for (int j = 0; j < HEAD_HIDDEN / 2; j++) t[j] = fma2(hv, wr[j], t[j]);
    }
    float r = sb2h;
    #pragma unroll
    for (int j = 0; j < HEAD_HIDDEN / 2; j++) {
        float lo, hi; upk(t[j], lo, hi);
        r += gelu(lo) * sw2[2*j] + gelu(hi) * sw2[2*j+1];
    }
    g_intr[n] = r;
}

// ---------------- per-layer node-side projections ----------------
// Ps = h @ pe_w1[l][0:24],  Pd = h @ pe_w1[l][24:48]   (each [N,84])
// Qs = h @ pv_w1[l][0:24],  Qd = h @ pv_w1[l][24:48]   (each [N,24])
__global__ void __launch_bounds__(256) k_nodeproj(
    const float* __restrict__ pe_w1_l, const float* __restrict__ pv_w1_l)
{
    __shared__ float we[48 * WPE];
    __shared__ float wv[48 * HIDDEN];
    int tid = threadIdx.x;
    for (int i = tid; i < 48 * EDGE_DIM; i += 256) {
        int k = i / EDGE_DIM, c = i - k * EDGE_DIM;
        we[k * WPE + c] = pe_w1_l[i];
    }
    for (int i = tid; i < 48 * HIDDEN; i += 256) wv[i] = pv_w1_l[i];
    __syncthreads();
    int n = blockIdx.x * 256 + tid;
    if (n >= N_NODES) return;

    ull h2[HIDDEN];
    #pragma unroll
    for (int k = 0; k < HIDDEN; k += 4) {
        float4 v = *(const float4*)(g_h + (size_t)n * HIDDEN + k);
        h2[k] = pk(v.x, v.x); h2[k+1] = pk(v.y, v.y);
        h2[k+2] = pk(v.z, v.z); h2[k+3] = pk(v.w, v.w);
    }
    #pragma unroll 1
    for (int ch = 0; ch < NCH; ch++) {
        int c0 = ch * CW;
        ull as[6], ad[6];
        #pragma unroll
        for (int j = 0; j < 6; j++) { as[j] = 0ULL; ad[j] = 0ULL; }
        #pragma unroll 4
        for (int k = 0; k < 24; k++) {
            const ulonglong2* ws = (const ulonglong2*)(we + k * WPE + c0);
            const ulonglong2* wd = (const ulonglong2*)(we + (k + 24) * WPE + c0);
            ulonglong2 s0 = ws[0], s1 = ws[1], s2 = ws[2];
            ulonglong2 d0 = wd[0], d1 = wd[1], d2 = wd[2];
            ull hk = h2[k];
            as[0]=fma2(hk,s0.x,as[0]); as[1]=fma2(hk,s0.y,as[1]);
            as[2]=fma2(hk,s1.x,as[2]); as[3]=fma2(hk,s1.y,as[3]);
            as[4]=fma2(hk,s2.x,as[4]); as[5]=fma2(hk,s2.y,as[5]);
            ad[0]=fma2(hk,d0.x,ad[0]); ad[1]=fma2(hk,d0.y,ad[1]);
            ad[2]=fma2(hk,d1.x,ad[2]); ad[3]=fma2(hk,d1.y,ad[3]);
            ad[4]=fma2(hk,d2.x,ad[4]); ad[5]=fma2(hk,d2.y,ad[5]);
        }
        float o[12];
        #pragma unroll
        for (int j = 0; j < 6; j++) upk(as[j], o[2*j], o[2*j+1]);
        #pragma unroll
        for (int k = 0; k < 12; k += 4)
            *(float4*)(g_Ps + (size_t)n * EDGE_DIM + c0 + k) = make_float4(o[k], o[k+1], o[k+2], o[k+3]);
        #pragma unroll
        for (int j = 0; j < 6; j++) upk(ad[j], o[2*j], o[2*j+1]);
        #pragma unroll
        for (int k = 0; k < 12; k += 4)
            *(float4*)(g_Pd + (size_t)n * EDGE_DIM + c0 + k) = make_float4(o[k], o[k+1], o[k+2], o[k+3]);
    }
    #pragma unroll 1
    for (int ch = 0; ch < 2; ch++) {
        int c0 = ch * CW;
        ull as[6], ad[6];
        #pragma unroll
        for (int j = 0; j < 6; j++) { as[j] = 0ULL; ad[j] = 0ULL; }
        #pragma unroll 4
        for (int k = 0; k < 24; k++) {
            const ulonglong2* ws = (const ulonglong2*)(wv + k * HIDDEN + c0);
            const ulonglong2* wd = (const ulonglong2*)(wv + (k + 24) * HIDDEN + c0);
            ulonglong2 s0 = ws[0], s1 = ws[1], s2 = ws[2];
            ulonglong2 d0 = wd[0], d1 = wd[1], d2 = wd[2];
            ull hk = h2[k];
            as[0]=fma2(hk,s0.x,as[0]); as[1]=fma2(hk,s0.y,as[1]);
            as[2]=fma2(hk,s1.x,as[2]); as[3]=fma2(hk,s1.y,as[3]);
            as[4]=fma2(hk,s2.x,as[4]); as[5]=fma2(hk,s2.y,as[5]);
            ad[0]=fma2(hk,d0.x,ad[0]); ad[1]=fma2(hk,d0.y,ad[1]);
            ad[2]=fma2(hk,d1.x,ad[2]); ad[3]=fma2(hk,d1.y,ad[3]);
            ad[4]=fma2(hk,d2.x,ad[4]); ad[5]=fma2(hk,d2.y,ad[5]);
        }
        float o[12];
        #pragma unroll
        for (int j = 0; j < 6; j++) upk(as[j], o[2*j], o[2*j+1]);
        #pragma unroll
        for (int k = 0; k < 12; k += 4)
            *(float4*)(g_Qs + (size_t)n * HIDDEN + c0 + k) = make_float4(o[k], o[k+1], o[k+2], o[k+3]);
        #pragma unroll
        for (int j = 0; j < 6; j++) upk(ad[j], o[2*j], o[2*j+1]);
        #pragma unroll
        for (int k = 0; k < 12; k += 4)
            *(float4*)(g_Qd + (size_t)n * HIDDEN + c0 + k) = make_float4(o[k], o[k+1], o[k+2], o[k+3]);
    }
}

// ---------------- fused per-layer edge kernel ----------------
// ein == nullptr means read g_e (layer > 0). Output always written to g_e.
#define EDGE_SMEM_FLOATS (2 * EDGE_DIM * ES_S + EDGE_DIM * WPE + 4 * EDGE_DIM + 2 * HIDDEN)
#define EDGE_SMEM_BYTES  (EDGE_SMEM_FLOATS * 4)

__global__ void __launch_bounds__(ETHREADS, 1) k_edge(
    const float* __restrict__ ein_p,
    const int* __restrict__ src, const int* __restrict__ dst,
    const float* __restrict__ we1,  const float* __restrict__ pb1,
    const float* __restrict__ we2,  const float* __restrict__ pb2,
    const float* __restrict__ neg,  const float* __restrict__ neb,
    const float* __restrict__ wv1,  const float* __restrict__ vb1,
    const float* __restrict__ wv2,  const float* __restrict__ vb2)
{
    extern __shared__ float smem[];
    float* es   = smem;                         // [84][257]
    float* us   = es + EDGE_DIM * ES_S;         // [84][257]
    float* sW   = us + EDGE_DIM * ES_S;         // [84][88] reusable weight buffer
    float* sb1  = sW + EDGE_DIM * WPE;          // pe_b1
    float* sb2  = sb1 + EDGE_DIM;               // pe_b2
    float* sg   = sb2 + EDGE_DIM;               // ne_g
    float* sbt  = sg + EDGE_DIM;                // ne_b
    float* svb1 = sbt + EDGE_DIM;               // pv_b1
    float* svb2 = svb1 + HIDDEN;                // pv_b2

    int tid = threadIdx.x;
    int base = blockIdx.x * TE;
    const float* ein = ein_p ? ein_p : g_e;

    // phase 1: coalesced e-tile load (transposed) + We1 + small params
    for (int i = tid; i < EDGE_DIM * TE; i += ETHREADS) {
        int ee = i / EDGE_DIM, k = i - ee * EDGE_DIM;
        es[k * ES_S + ee] = ein[(size_t)(base + ee) * EDGE_DIM + k];
    }
    for (int i = tid; i < EDGE_DIM * EDGE_DIM; i += ETHREADS) {
        int k = i / EDGE_DIM, c = i - k * EDGE_DIM;
        sW[k * WPE + c] = we1[i];
    }
    if (tid < EDGE_DIM) { sb1[tid] = pb1[tid]; sb2[tid] = pb2[tid]; sg[tid] = neg[tid]; sbt[tid] = neb[tid]; }
    if (tid < HIDDEN)   { svb1[tid] = vb1[tid]; svb2[tid] = vb2[tid]; }
    __syncthreads();

    int ed = base + tid;           // grid exactly covers N_EDGES (800000 % 256 == 0)
    int s = src[ed], d = dst[ed];
    const float* ps = g_Ps + (size_t)s * EDGE_DIM;
    const float* pd = g_Pd + (size_t)d * EDGE_DIM;
    float* ecol = es + tid;
    float* ucol = us + tid;

    // phase 2: u = gelu(Ps[s] + Pd[d] + e @ We1 + pe_b1)
    #pragma unroll 1
    for (int ch = 0; ch < NCH; ch++) {
        int c0 = ch * CW;
        float4 a0 = *(const float4*)(ps + c0);
        float4 a1 = *(const float4*)(ps + c0 + 4);
        float4 a2 = *(const float4*)(ps + c0 + 8);
        float4 b0 = *(const float4*)(pd + c0);
        float4 b1 = *(const float4*)(pd + c0 + 4);
        float4 b2 = *(const float4*)(pd + c0 + 8);
        ull acc[6];
        acc[0] = pk(a0.x + b0.x + sb1[c0+0],  a0.y + b0.y + sb1[c0+1]);
        acc[1] = pk(a0.z + b0.z + sb1[c0+2],  a0.w + b0.w + sb1[c0+3]);
        acc[2] = pk(a1.x + b1.x + sb1[c0+4],  a1.y + b1.y + sb1[c0+5]);
        acc[3] = pk(a1.z + b1.z + sb1[c0+6],  a1.w + b1.w + sb1[c0+7]);
        acc[4] = pk(a2.x + b2.x + sb1[c0+8],  a2.y + b2.y + sb1[c0+9]);
        acc[5] = pk(a2.z + b2.z + sb1[c0+10], a2.w + b2.w + sb1[c0+11]);
        const float* wbase = sW + c0;
        #pragma unroll 4
        for (int k = 0; k < EDGE_DIM; k++) {
            float ek = ecol[k * ES_S];
            ull e2 = pk(ek, ek);
            const ulonglong2* w = (const ulonglong2*)(wbase + k * WPE);
            ulonglong2 w0 = w[0], w1 = w[1], w2 = w[2];
            acc[0] = fma2(e2, w0.x, acc[0]);  acc[1] = fma2(e2, w0.y, acc[1]);
            acc[2] = fma2(e2, w1.x, acc[2]);  acc[3] = fma2(e2, w1.y, acc[3]);
            acc[4] = fma2(e2, w2.x, acc[4]);  acc[5] = fma2(e2, w2.y, acc[5]);
        }
        #pragma unroll
        for (int j = 0; j < 6; j++) {
            float lo, hi; upk(acc[j], lo, hi);
            ucol[(c0 + 2*j)     * ES_S] = gelu(lo);
            ucol[(c0 + 2*j + 1) * ES_S] = gelu(hi);
        }
    }
    __syncthreads();

    // phase 3: reload sW with pe_w2
    for (int i = tid; i < EDGE_DIM * EDGE_DIM; i += ETHREADS) {
        int k = i / EDGE_DIM, c = i - k * EDGE_DIM;
        sW[k * WPE + c] = we2[i];
    }
    __syncthreads();

    // phase 4: e_msg = u @ pe_w2 + pe_b2;  r = e + e_msg;  LayerNorm -> es
    float sum = 0.0f, sq = 0.0f;
    #pragma unroll 1
    for (int ch = 0; ch < NCH; ch++) {
        int c0 = ch * CW;
        ull acc[6];
        #pragma unroll
        for (int j = 0; j < 6; j++) acc[j] = pk(sb2[c0 + 2*j], sb2[c0 + 2*j + 1]);
        const float* wbase = sW + c0;
        #pragma unroll 4
        for (int k = 0; k < EDGE_DIM; k++) {
            float uk = ucol[k * ES_S];
            ull u2 = pk(uk, uk);
            const ulonglong2* w = (const ulonglong2*)(wbase + k * WPE);
            ulonglong2 w0 = w[0], w1 = w[1], w2 = w[2];
            acc[0] = fma2(u2, w0.x, acc[0]);  acc[1] = fma2(u2, w0.y, acc[1]);
            acc[2] = fma2(u2, w1.x, acc[2]);  acc[3] = fma2(u2, w1.y, acc[3]);
            acc[4] = fma2(u2, w2.x, acc[4]);  acc[5] = fma2(u2, w2.y, acc[5]);
        }
        #pragma unroll
        for (int j = 0; j < 6; j++) {
            float lo, hi; upk(acc[j], lo, hi);
            float r0 = ecol[(c0 + 2*j)     * ES_S] + lo;
            float r1 = ecol[(c0 + 2*j + 1) * ES_S] + hi;
            sum += r0 + r1; sq += r0 * r0 + r1 * r1;
            ecol[(c0 + 2*j)     * ES_S] = r0;
            ecol[(c0 + 2*j + 1) * ES_S] = r1;
        }
    }
    {
        float mean = sum * (1.0f / EDGE_DIM);
        float var  = fmaxf(sq * (1.0f / EDGE_DIM) - mean * mean, 0.0f);
        float rstd = rsqrtf(var + LN_EPS);
        #pragma unroll 4
        for (int c = 0; c < EDGE_DIM; c++) {
            float r = ecol[c * ES_S];
            ecol[c * ES_S] = (r - mean) * rstd * sg[c] + sbt[c];
        }
    }
    __syncthreads();

    // phase 5: reload sW with Wv1 (84x24) then Wv2 (24x24)
    for (int i = tid; i < EDGE_DIM * HIDDEN; i += ETHREADS) sW[i] = wv1[i];
    for (int i = tid; i < HIDDEN * HIDDEN; i += ETHREADS) sW[EDGE_DIM * HIDDEN + i] = wv2[i];
    __syncthreads();

    // phase 6: m = (gelu(Qs+Qd+e@Wv1+b1)) @ Wv2 + b2;  scatter-add into agg[dst]
    {
        const float* qs = g_Qs + (size_t)s * HIDDEN;
        const float* qd = g_Qd + (size_t)d * HIDDEN;
        float qv[HIDDEN], dv[HIDDEN];
        #pragma unroll
        for (int k = 0; k < HIDDEN; k += 4) {
            float4 a = *(const float4*)(qs + k);
            float4 b = *(const float4*)(qd + k);
            qv[k] = a.x; qv[k+1] = a.y; qv[k+2] = a.z; qv[k+3] = a.w;
            dv[k] = b.x; dv[k+1] = b.y; dv[k+2] = b.z; dv[k+3] = b.w;
        }
        ull acc[12];
        #pragma unroll
        for (int j = 0; j < 12; j++)
            acc[j] = pk(qv[2*j] + dv[2*j] + svb1[2*j], qv[2*j+1] + dv[2*j+1] + svb1[2*j+1]);
        #pragma unroll 2
        for (int k = 0; k < EDGE_DIM; k++) {
            float ek = ecol[k * ES_S];
            ull e2 = pk(ek, ek);
            const ulonglong2* w = (const ulonglong2*)(sW + k * HIDDEN);
            ulonglong2 w0 = w[0], w1 = w[1], w2 = w[2], w3 = w[3], w4 = w[4], w5 = w[5];
            acc[0] = fma2(e2, w0.x, acc[0]);   acc[1] = fma2(e2, w0.y, acc[1]);
            acc[2] = fma2(e2, w1.x, acc[2]);   acc[3] = fma2(e2, w1.y, acc[3]);
            acc[4] = fma2(e2, w2.x, acc[4]);   acc[5] = fma2(e2, w2.y, acc[5]);
            acc[6] = fma2(e2, w3.x, acc[6]);   acc[7] = fma2(e2, w3.y, acc[7]);
            acc[8] = fma2(e2, w4.x, acc[8]);   acc[9] = fma2(e2, w4.y, acc[9]);
            acc[10] = fma2(e2, w5.x, acc[10]); acc[11] = fma2(e2, w5.y, acc[11]);
        }
        float vv[HIDDEN];
        #pragma unroll
        for (int j = 0; j < 12; j++) {
            float lo, hi; upk(acc[j], lo, hi);
            vv[2*j] = gelu(lo); vv[2*j+1] = gelu(hi);
        }
        ull m[12];
        #pragma unroll
        for (int j = 0; j < 12; j++) m[j] = pk(svb2[2*j], svb2[2*j+1]);
        #pragma unroll
        for (int k = 0; k < HIDDEN; k++) {
            ull v2 = pk(vv[k], vv[k]);
            const ulonglong2* w = (const ulonglong2*)(sW + EDGE_DIM * HIDDEN + k * HIDDEN);
            ulonglong2 w0 = w[0], w1 = w[1], w2 = w[2], w3 = w[3], w4 = w[4], w5 = w[5];
            m[0] = fma2(v2, w0.x, m[0]);   m[1] = fma2(v2, w0.y, m[1]);
            m[2] = fma2(v2, w1.x, m[2]);   m[3] = fma2(v2, w1.y, m[3]);
            m[4] = fma2(v2, w2.x, m[4]);   m[5] = fma2(v2, w2.y, m[5]);
            m[6] = fma2(v2, w3.x, m[6]);   m[7] = fma2(v2, w3.y, m[7]);
            m[8] = fma2(v2, w4.x, m[8]);   m[9] = fma2(v2, w4.y, m[9]);
            m[10] = fma2(v2, w5.x, m[10]); m[11] = fma2(v2, w5.y, m[11]);
        }
        float* ag = g_agg + (size_t)d * HIDDEN;
        #pragma unroll
        for (int j = 0; j < 12; j++) {
            float lo, hi; upk(m[j], lo, hi);
            atomicAdd(ag + 2*j, lo);
            atomicAdd(ag + 2*j + 1, hi);
        }
    }

    // phase 7: coalesced write of the new e tile
    for (int i = tid; i < EDGE_DIM * TE; i += ETHREADS) {
        int ee = i / EDGE_DIM, k = i - ee * EDGE_DIM;
        g_e[(size_t)(base + ee) * EDGE_DIM + k] = es[k * ES_S + ee];
    }
}

// ---------------- node update: h = LN(h + agg / count) ----------------
__global__ void k_nodeup(const float* __restrict__ nvg, const float* __restrict__ nvb) {
    int n = blockIdx.x * blockDim.x + threadIdx.x;
    if (n >= N_NODES) return;
    float inv = 1.0f / fmaxf(g_cnt[n], 1.0f);
    float r[HIDDEN];
    float sum = 0.0f, sq = 0.0f;
    #pragma unroll
    for (int k = 0; k < HIDDEN; k += 4) {
        float4 hv = *(const float4*)(g_h + (size_t)n * HIDDEN + k);
        float4 av = *(const float4*)(g_agg + (size_t)n * HIDDEN + k);
        r[k]   = hv.x + av.x * inv; r[k+1] = hv.y + av.y * inv;
        r[k+2] = hv.z + av.z * inv; r[k+3] = hv.w + av.w * inv;
        sum += r[k] + r[k+1] + r[k+2] + r[k+3];
        sq  += r[k]*r[k] + r[k+1]*r[k+1] + r[k+2]*r[k+2] + r[k+3]*r[k+3];
    }
    float mean = sum * (1.0f / HIDDEN);
    float var  = fmaxf(sq * (1.0f / HIDDEN) - mean * mean, 0.0f);
    float rstd = rsqrtf(var + LN_EPS);
    #pragma unroll
    for (int k = 0; k < HIDDEN; k++) r[k] = (r[k] - mean) * rstd * nvg[k] + nvb[k];
    #pragma unroll
    for (int k = 0; k < HIDDEN; k += 4)
        *(float4*)(g_h + (size_t)n * HIDDEN + k) = make_float4(r[k], r[k+1], r[k+2], r[k+3]);
}

// ---------------- context head + final output ----------------
__global__ void __launch_bounds__(256) k_out(
    const float* __restrict__ ch_w1, const float* __restrict__ ch_b1,
    const float* __restrict__ ch_w2, const float* __restrict__ ch_b2,
    const float* __restrict__ mu, float* __restrict__ out)
{
    __shared__ float sw1[HIDDEN * HEAD_HIDDEN];
    __shared__ float sb1h[HEAD_HIDDEN];
    __shared__ float sw2[HEAD_HIDDEN];
    __shared__ float sb2h, smu;
    int tid = threadIdx.x;
    for (int i = tid; i < HIDDEN * HEAD_HIDDEN; i += 256) sw1[i] = ch_w1[i];
    if (tid < HEAD_HIDDEN) { sb1h[tid] = ch_b1[tid]; sw2[tid] = ch_w2[tid]; }
    if (tid == 0) { sb2h = ch_b2[0]; smu = mu[0]; }
    __syncthreads();
    int n = blockIdx.x * 256 + tid;
    if (n >= N_NODES) return;

    float h[HIDDEN];
    #pragma unroll
    for (int k = 0; k < HIDDEN; k += 4) {
        float4 v = *(const float4*)(g_h + (size_t)n * HIDDEN + k);
        h[k] = v.x; h[k+1] = v.y; h[k+2] = v.z; h[k+3] = v.w;
    }
    ull t[HEAD_HIDDEN / 2];
    #pragma unroll
    for (int j = 0; j < HEAD_HIDDEN / 2; j++) t[j] = pk(sb1h[2*j], sb1h[2*j+1]);
    #pragma unroll 4
    for (int k = 0; k < HIDDEN; k++) {
        ull hv = pk(h[k], h[k]);
        const ull* wr = (const ull*)(sw1 + k * HEAD_HIDDEN);
        #pragma unroll
        for (int j = 0; j < HEAD_HIDDEN / 2; j++) t[j] = fma2(hv, wr[j], t[j]);
    }
    float r = sb2h;
    #pragma unroll
    for (int j = 0; j < HEAD_HIDDEN / 2; j++) {
        float lo, hi; upk(t[j], lo, hi);
        r += gelu(lo) * sw2[2*j] + gelu(hi) * sw2[2*j+1];
    }
    out[n] = smu + g_intr[n] + r;
}

// ---------------- launch ----------------
extern "C" void kernel_launch(void* const* d_in, const int* in_sizes, int n_in,
                              void* d_out, int out_size) {
    (void)in_sizes; (void)n_in; (void)out_size;
    const float* x         = (const float*)d_in[0];
    const float* edge_attr = (const float*)d_in[1];
    const float* node_w    = (const float*)d_in[2];
    const float* node_b    = (const float*)d_in[3];
    const float* ih_w1     = (const float*)d_in[4];
    const float* ih_b1     = (const float*)d_in[5];
    const float* ih_w2     = (const float*)d_in[6];
    const float* ih_b2     = (const float*)d_in[7];
    const float* pe_w1     = (const float*)d_in[8];
    const float* pe_b1     = (const float*)d_in[9];
    const float* pe_w2     = (const float*)d_in[10];
    const float* pe_b2     = (const float*)d_in[11];
    const float* pv_w1     = (const float*)d_in[12];
    const float* pv_b1     = (const float*)d_in[13];
    const float* pv_w2     = (const float*)d_in[14];
    const float* pv_b2     = (const float*)d_in[15];
    const float* ne_g      = (const float*)d_in[16];
    const float* ne_b      = (const float*)d_in[17];
    const float* nv_g      = (const float*)d_in[18];
    const float* nv_b      = (const float*)d_in[19];
    const float* ch_w1     = (const float*)d_in[20];
    const float* ch_b1     = (const float*)d_in[21];
    const float* ch_w2     = (const float*)d_in[22];
    const float* ch_b2     = (const float*)d_in[23];
    const float* mu        = (const float*)d_in[24];
    const int*   eidx      = (const int*)d_in[25];
    const int* src = eidx;
    const int* dst = eidx + N_EDGES;
    float* out = (float*)d_out;

    cudaFuncSetAttribute(k_edge, cudaFuncAttributeMaxDynamicSharedMemorySize, EDGE_SMEM_BYTES);

    const int NB_N = (N_NODES + 255) / 256;
    const int NB_E = N_EDGES / 256;          // 3125, exact
    const int NB_A = (N_NODES * HIDDEN + 255) / 256;

    k_input<<<NB_N, 256>>>(x, node_w, node_b, ih_w1, ih_b1, ih_w2, ih_b2);
    k_zero_cnt<<<NB_N, 256>>>();
    k_count<<<NB_E, 256>>>(dst);

    for (int i = 0; i < DEPTH; i++) {
        const float* pe1 = pe_w1 + (size_t)i * 132 * EDGE_DIM;
        const float* pv1 = pv_w1 + (size_t)i * 132 * HIDDEN;
        k_zero_agg<<<NB_A, 256>>>();
        k_nodeproj<<<NB_N, 256>>>(pe1, pv1);
        k_edge<<<NB_E, ETHREADS, EDGE_SMEM_BYTES>>>(
            (i == 0) ? edge_attr : (const float*)nullptr,
            src, dst,
            pe1 + 48 * EDGE_DIM,                 // We1: rows 48..131 of pe_w1[i]
            pe_b1 + (size_t)i * EDGE_DIM,
            pe_w2 + (size_t)i * EDGE_DIM * EDGE_DIM,
            pe_b2 + (size_t)i * EDGE_DIM,
            ne_g + (size_t)i * EDGE_DIM,
            ne_b + (size_t)i * EDGE_DIM,
            pv1 + 48 * HIDDEN,                   // Wv1: rows 48..131 of pv_w1[i]
            pv_b1 + (size_t)i * HIDDEN,
            pv_w2 + (size_t)i * HIDDEN * HIDDEN,
            pv_b2 + (size_t)i * HIDDEN);
        k_nodeup<<<NB_N, 256>>>(nv_g + (size_t)i * HIDDEN, nv_b + (size_t)i * HIDDEN);
    }

    k_out<<<NB_N, 256>>>(ch_w1, ch_b1, ch_w2, ch_b2, mu, out);
}

// round 13
// speedup vs baseline: 1.1625x; 1.1625x over previous
#include <cuda_runtime.h>
#include <cuda_bf16.h>
#include <math.h>

#define N_NODES   100000
#define N_EDGES   800000
#define NODE_IN   32
#define EDGE_DIM  84
#define HIDDEN    24
#define HEAD_HIDDEN 20
#define DEPTH     2
#define LN_EPS    1e-5f

#define TE 256            // edges per block
#define ETHREADS 256
#define ES_S (TE + 1)     // 257: stride ≡ 1 mod 32 -> conflict-free everywhere
#define SWP 96            // padded col count for 84x84 weights (16B-aligned 12-col groups)
#define WV1P 32           // padded col count for 84x24 weight

typedef unsigned long long ull;

// ---------------- packed f32x2 helpers (Blackwell FFMA2) ----------------
__device__ __forceinline__ ull pk(float lo, float hi) {
    ull r; asm("mov.b64 %0, {%1,%2};" : "=l"(r) : "f"(lo), "f"(hi)); return r;
}
__device__ __forceinline__ void upk(ull v, float& lo, float& hi) {
    asm("mov.b64 {%0,%1}, %2;" : "=f"(lo), "=f"(hi) : "l"(v));
}
__device__ __forceinline__ ull fma2(ull a, ull b, ull c) {
    ull d; asm("fma.rn.f32x2 %0, %1, %2, %3;" : "=l"(d) : "l"(a), "l"(b), "l"(c)); return d;
}
__device__ __forceinline__ float gelu(float x) {
    return 0.5f * x * (1.0f + erff(x * 0.7071067811865476f));
}

// ---------------- scratch (device globals: allocation-free) ----------------
__device__ float g_h[N_NODES * HIDDEN];
__device__ float g_intr[N_NODES];
__device__ float g_cnt[N_NODES];
__device__ float g_Ps[N_NODES * EDGE_DIM];
__device__ float g_Pd[N_NODES * EDGE_DIM];
__device__ float g_Qs[N_NODES * HIDDEN];
__device__ float g_Qd[N_NODES * HIDDEN];
__device__ float g_agg[N_NODES * HIDDEN];
__device__ float g_e[(size_t)N_EDGES * EDGE_DIM];

// ---------------- small utility kernels ----------------
__global__ void k_zero_cnt() {
    int i = blockIdx.x * blockDim.x + threadIdx.x;
    if (i < N_NODES) g_cnt[i] = 0.0f;
}
__global__ void k_zero_agg() {
    int i = blockIdx.x * blockDim.x + threadIdx.x;
    if (i < N_NODES * HIDDEN) g_agg[i] = 0.0f;
}
__global__ void k_count(const int* __restrict__ dst) {
    int e = blockIdx.x * blockDim.x + threadIdx.x;
    if (e < N_EDGES) atomicAdd(&g_cnt[dst[e]], 1.0f);
}

// ---------------- input projection + intrinsic head ----------------
__global__ void __launch_bounds__(256) k_input(
    const float* __restrict__ x, const float* __restrict__ node_w,
    const float* __restrict__ node_b, const float* __restrict__ ih_w1,
    const float* __restrict__ ih_b1, const float* __restrict__ ih_w2,
    const float* __restrict__ ih_b2)
{
    __shared__ float sw[NODE_IN * HIDDEN];
    __shared__ float sbias[HIDDEN];
    __shared__ float sw1[HIDDEN * HEAD_HIDDEN];
    __shared__ float sb1h[HEAD_HIDDEN];
    __shared__ float sw2[HEAD_HIDDEN];
    __shared__ float sb2h;
    int tid = threadIdx.x;
    for (int i = tid; i < NODE_IN * HIDDEN; i += 256) sw[i] = node_w[i];
    for (int i = tid; i < HIDDEN * HEAD_HIDDEN; i += 256) sw1[i] = ih_w1[i];
    if (tid < HIDDEN) sbias[tid] = node_b[tid];
    if (tid < HEAD_HIDDEN) { sb1h[tid] = ih_b1[tid]; sw2[tid] = ih_w2[tid]; }
    if (tid == 0) sb2h = ih_b2[0];
    __syncthreads();
    int n = blockIdx.x * 256 + tid;
    if (n >= N_NODES) return;

    float xr[NODE_IN];
    #pragma unroll
    for (int k = 0; k < NODE_IN; k += 4) {
        float4 v = *(const float4*)(x + (size_t)n * NODE_IN + k);
        xr[k] = v.x; xr[k+1] = v.y; xr[k+2] = v.z; xr[k+3] = v.w;
    }
    ull acc[HIDDEN / 2];
    #pragma unroll
    for (int j = 0; j < HIDDEN / 2; j++) acc[j] = pk(sbias[2*j], sbias[2*j+1]);
    #pragma unroll 4
    for (int k = 0; k < NODE_IN; k++) {
        ull xv = pk(xr[k], xr[k]);
        const ulonglong2* wr = (const ulonglong2*)(sw + k * HIDDEN);
        ulonglong2 w0 = wr[0], w1 = wr[1], w2 = wr[2], w3 = wr[3], w4 = wr[4], w5 = wr[5];
        acc[0]=fma2(xv,w0.x,acc[0]);  acc[1]=fma2(xv,w0.y,acc[1]);
        acc[2]=fma2(xv,w1.x,acc[2]);  acc[3]=fma2(xv,w1.y,acc[3]);
        acc[4]=fma2(xv,w2.x,acc[4]);  acc[5]=fma2(xv,w2.y,acc[5]);
        acc[6]=fma2(xv,w3.x,acc[6]);  acc[7]=fma2(xv,w3.y,acc[7]);
        acc[8]=fma2(xv,w4.x,acc[8]);  acc[9]=fma2(xv,w4.y,acc[9]);
        acc[10]=fma2(xv,w5.x,acc[10]); acc[11]=fma2(xv,w5.y,acc[11]);
    }
    float h[HIDDEN];
    #pragma unroll
    for (int j = 0; j < HIDDEN / 2; j++) upk(acc[j], h[2*j], h[2*j+1]);
    #pragma unroll
    for (int k = 0; k < HIDDEN; k += 4)
        *(float4*)(g_h + (size_t)n * HIDDEN + k) = make_float4(h[k], h[k+1], h[k+2], h[k+3]);

    ull t[HEAD_HIDDEN / 2];
    #pragma unroll
    for (int j = 0; j < HEAD_HIDDEN / 2; j++) t[j] = pk(sb1h[2*j], sb1h[2*j+1]);
    #pragma unroll 4
    for (int k = 0; k < HIDDEN; k++) {
        ull hv = pk(h[k], h[k]);
        const ull* wr = (const ull*)(sw1 + k * HEAD_HIDDEN);
        #pragma unroll
        for (int j = 0; j < HEAD_HIDDEN / 2; j++) t[j] = fma2(hv, wr[j], t[j]);
    }
    float r = sb2h;
    #pragma unroll
    for (int j = 0; j < HEAD_HIDDEN / 2; j++) {
        float lo, hi; upk(t[j], lo, hi);
        r += gelu(lo) * sw2[2*j] + gelu(hi) * sw2[2*j+1];
    }
    g_intr[n] = r;
}

// ---------------- per-layer node-side projections ----------------
__global__ void __launch_bounds__(256) k_nodeproj(
    const float* __restrict__ pe_w1_l, const float* __restrict__ pv_w1_l)
{
    __shared__ float we[48 * 88];
    __shared__ float wv[48 * HIDDEN];
    int tid = threadIdx.x;
    for (int i = tid; i < 48 * EDGE_DIM; i += 256) {
        int k = i / EDGE_DIM, c = i - k * EDGE_DIM;
        we[k * 88 + c] = pe_w1_l[i];
    }
    for (int i = tid; i < 48 * HIDDEN; i += 256) wv[i] = pv_w1_l[i];
    __syncthreads();
    int n = blockIdx.x * 256 + tid;
    if (n >= N_NODES) return;

    ull h2[HIDDEN];
    #pragma unroll
    for (int k = 0; k < HIDDEN; k += 4) {
        float4 v = *(const float4*)(g_h + (size_t)n * HIDDEN + k);
        h2[k] = pk(v.x, v.x); h2[k+1] = pk(v.y, v.y);
        h2[k+2] = pk(v.z, v.z); h2[k+3] = pk(v.w, v.w);
    }
    #pragma unroll 1
    for (int ch = 0; ch < 7; ch++) {
        int c0 = ch * 12;
        ull as[6], ad[6];
        #pragma unroll
        for (int j = 0; j < 6; j++) { as[j] = 0ULL; ad[j] = 0ULL; }
        #pragma unroll 4
        for (int k = 0; k < 24; k++) {
            const ulonglong2* ws = (const ulonglong2*)(we + k * 88 + c0);
            const ulonglong2* wd = (const ulonglong2*)(we + (k + 24) * 88 + c0);
            ulonglong2 s0 = ws[0], s1 = ws[1], s2 = ws[2];
            ulonglong2 d0 = wd[0], d1 = wd[1], d2 = wd[2];
            ull hk = h2[k];
            as[0]=fma2(hk,s0.x,as[0]); as[1]=fma2(hk,s0.y,as[1]);
            as[2]=fma2(hk,s1.x,as[2]); as[3]=fma2(hk,s1.y,as[3]);
            as[4]=fma2(hk,s2.x,as[4]); as[5]=fma2(hk,s2.y,as[5]);
            ad[0]=fma2(hk,d0.x,ad[0]); ad[1]=fma2(hk,d0.y,ad[1]);
            ad[2]=fma2(hk,d1.x,ad[2]); ad[3]=fma2(hk,d1.y,ad[3]);
            ad[4]=fma2(hk,d2.x,ad[4]); ad[5]=fma2(hk,d2.y,ad[5]);
        }
        float o[12];
        #pragma unroll
        for (int j = 0; j < 6; j++) upk(as[j], o[2*j], o[2*j+1]);
        #pragma unroll
        for (int k = 0; k < 12; k += 4)
            *(float4*)(g_Ps + (size_t)n * EDGE_DIM + c0 + k) = make_float4(o[k], o[k+1], o[k+2], o[k+3]);
        #pragma unroll
        for (int j = 0; j < 6; j++) upk(ad[j], o[2*j], o[2*j+1]);
        #pragma unroll
        for (int k = 0; k < 12; k += 4)
            *(float4*)(g_Pd + (size_t)n * EDGE_DIM + c0 + k) = make_float4(o[k], o[k+1], o[k+2], o[k+3]);
    }
    #pragma unroll 1
    for (int ch = 0; ch < 2; ch++) {
        int c0 = ch * 12;
        ull as[6], ad[6];
        #pragma unroll
        for (int j = 0; j < 6; j++) { as[j] = 0ULL; ad[j] = 0ULL; }
        #pragma unroll 4
        for (int k = 0; k < 24; k++) {
            const ulonglong2* ws = (const ulonglong2*)(wv + k * HIDDEN + c0);
            const ulonglong2* wd = (const ulonglong2*)(wv + (k + 24) * HIDDEN + c0);
            ulonglong2 s0 = ws[0], s1 = ws[1], s2 = ws[2];
            ulonglong2 d0 = wd[0], d1 = wd[1], d2 = wd[2];
            ull hk = h2[k];
            as[0]=fma2(hk,s0.x,as[0]); as[1]=fma2(hk,s0.y,as[1]);
            as[2]=fma2(hk,s1.x,as[2]); as[3]=fma2(hk,s1.y,as[3]);
            as[4]=fma2(hk,s2.x,as[4]); as[5]=fma2(hk,s2.y,as[5]);
            ad[0]=fma2(hk,d0.x,ad[0]); ad[1]=fma2(hk,d0.y,ad[1]);
            ad[2]=fma2(hk,d1.x,ad[2]); ad[3]=fma2(hk,d1.y,ad[3]);
            ad[4]=fma2(hk,d2.x,ad[4]); ad[5]=fma2(hk,d2.y,ad[5]);
        }
        float o[12];
        #pragma unroll
        for (int j = 0; j < 6; j++) upk(as[j], o[2*j], o[2*j+1]);
        #pragma unroll
        for (int k = 0; k < 12; k += 4)
            *(float4*)(g_Qs + (size_t)n * HIDDEN + c0 + k) = make_float4(o[k], o[k+1], o[k+2], o[k+3]);
        #pragma unroll
        for (int j = 0; j < 6; j++) upk(ad[j], o[2*j], o[2*j+1]);
        #pragma unroll
        for (int k = 0; k < 12; k += 4)
            *(float4*)(g_Qd + (size_t)n * HIDDEN + c0 + k) = make_float4(o[k], o[k+1], o[k+2], o[k+3]);
    }
}

// ---------------- fused per-layer edge kernel (register-blocked GEMMs) ----------------
// SMEM layout (floats):
//   es   [84][257]  = 21588
//   us   [84][257]  = 21588
//   sW   [84][96]   = 8064   (phase 2: We1 padded; phase 4: pe_w2 padded)
//   sWv1 [84][32]   = 2688
//   sWv2 [24][24]   = 576
//   sb1[96] sb2[96] sg[84] sbt[84] svb1[24] svb2[24] = 408
#define EDGE_SMEM_FLOATS (2 * EDGE_DIM * ES_S + EDGE_DIM * SWP + EDGE_DIM * WV1P + 576 + 408)
#define EDGE_SMEM_BYTES  (EDGE_SMEM_FLOATS * 4)

__global__ void __launch_bounds__(ETHREADS, 1) k_edge(
    const float* __restrict__ ein_p,
    const int* __restrict__ src, const int* __restrict__ dst,
    const float* __restrict__ we1,  const float* __restrict__ pb1,
    const float* __restrict__ we2,  const float* __restrict__ pb2,
    const float* __restrict__ neg,  const float* __restrict__ neb,
    const float* __restrict__ wv1,  const float* __restrict__ vb1,
    const float* __restrict__ wv2,  const float* __restrict__ vb2,
    int store_e)
{
    extern __shared__ float smem[];
    float* es   = smem;
    float* us   = es + EDGE_DIM * ES_S;
    float* sW   = us + EDGE_DIM * ES_S;
    float* sWv1 = sW + EDGE_DIM * SWP;
    float* sWv2 = sWv1 + EDGE_DIM * WV1P;
    float* sb1  = sWv2 + 576;
    float* sb2  = sb1 + 96;
    float* sg   = sb2 + 96;
    float* sbt  = sg + EDGE_DIM;
    float* svb1 = sbt + EDGE_DIM;
    float* svb2 = svb1 + HIDDEN;

    int tid = threadIdx.x;
    int base = blockIdx.x * TE;
    const float* ein = ein_p ? ein_p : g_e;

    // ---- P1: stage e tile (transposed) + all weights/params ----
    for (int i = tid; i < EDGE_DIM * TE; i += ETHREADS) {
        int ee = i / EDGE_DIM, k = i - ee * EDGE_DIM;
        es[k * ES_S + ee] = ein[(size_t)(base + ee) * EDGE_DIM + k];
    }
    for (int i = tid; i < EDGE_DIM * SWP; i += ETHREADS) {
        int k = i / SWP, c = i - k * SWP;
        sW[i] = (c < EDGE_DIM) ? we1[k * EDGE_DIM + c] : 0.0f;
    }
    for (int i = tid; i < EDGE_DIM * WV1P; i += ETHREADS) {
        int k = i / WV1P, c = i - k * WV1P;
        sWv1[i] = (c < HIDDEN) ? wv1[k * HIDDEN + c] : 0.0f;
    }
    for (int i = tid; i < HIDDEN * HIDDEN; i += ETHREADS) sWv2[i] = wv2[i];
    if (tid < EDGE_DIM) { sb1[tid] = pb1[tid]; sb2[tid] = pb2[tid]; sg[tid] = neg[tid]; sbt[tid] = neb[tid]; }
    if (tid >= EDGE_DIM && tid < 96) { sb1[tid] = 0.0f; sb2[tid] = 0.0f; }
    if (tid < HIDDEN) { svb1[tid] = vb1[tid]; svb2[tid] = vb2[tid]; }
    __syncthreads();

    int wid = tid >> 5, lane = tid & 31;

    // ---- P2: u = gelu(Ps[s] + Pd[d] + e @ We1 + b1) ----
    // warp w (0..6) owns cols [12w, 12w+12); thread owns 8 edges lane+32j
    if (wid < 7) {
        int c0 = wid * 12;
        ull acc[8][6];
        #pragma unroll
        for (int j = 0; j < 8; j++)
            #pragma unroll
            for (int c = 0; c < 6; c++) acc[j][c] = 0ULL;
        const float* eb = es + lane;
        const float* wb = sW + c0;
        #pragma unroll 2
        for (int k = 0; k < EDGE_DIM; k++) {
            const ulonglong2* wr = (const ulonglong2*)(wb + k * SWP);
            ulonglong2 w0 = wr[0], w1 = wr[1], w2 = wr[2];
            const float* er = eb + k * ES_S;
            #pragma unroll
            for (int j = 0; j < 8; j++) {
                float ev = er[32 * j];
                ull e2 = pk(ev, ev);
                acc[j][0] = fma2(e2, w0.x, acc[j][0]);
                acc[j][1] = fma2(e2, w0.y, acc[j][1]);
                acc[j][2] = fma2(e2, w1.x, acc[j][2]);
                acc[j][3] = fma2(e2, w1.y, acc[j][3]);
                acc[j][4] = fma2(e2, w2.x, acc[j][4]);
                acc[j][5] = fma2(e2, w2.y, acc[j][5]);
            }
        }
        #pragma unroll
        for (int j = 0; j < 8; j++) {
            int ed = base + lane + 32 * j;
            int s = src[ed], d = dst[ed];
            const float* ps = g_Ps + (size_t)s * EDGE_DIM + c0;
            const float* pd = g_Pd + (size_t)d * EDGE_DIM + c0;
            float4 pa0 = *(const float4*)(ps);
            float4 pa1 = *(const float4*)(ps + 4);
            float4 pa2 = *(const float4*)(ps + 8);
            float4 pb0 = *(const float4*)(pd);
            float4 pb1v = *(const float4*)(pd + 4);
            float4 pb2v = *(const float4*)(pd + 8);
            float add[12] = { pa0.x+pb0.x, pa0.y+pb0.y, pa0.z+pb0.z, pa0.w+pb0.w,
                              pa1.x+pb1v.x, pa1.y+pb1v.y, pa1.z+pb1v.z, pa1.w+pb1v.w,
                              pa2.x+pb2v.x, pa2.y+pb2v.y, pa2.z+pb2v.z, pa2.w+pb2v.w };
            float* uc = us + lane + 32 * j;
            #pragma unroll
            for (int c = 0; c < 6; c++) {
                float lo, hi; upk(acc[j][c], lo, hi);
                uc[(c0 + 2*c)     * ES_S] = gelu(lo + add[2*c]   + sb1[c0 + 2*c]);
                uc[(c0 + 2*c + 1) * ES_S] = gelu(hi + add[2*c+1] + sb1[c0 + 2*c + 1]);
            }
        }
    }
    __syncthreads();

    // ---- P3: reload sW with pe_w2 (padded) ----
    for (int i = tid; i < EDGE_DIM * SWP; i += ETHREADS) {
        int k = i / SWP, c = i - k * SWP;
        sW[i] = (c < EDGE_DIM) ? we2[k * EDGE_DIM + c] : 0.0f;
    }
    __syncthreads();

    // ---- P4: r = e + (u @ pe_w2 + b2)  -> es (un-normalized residual) ----
    if (wid < 7) {
        int c0 = wid * 12;
        ull acc[8][6];
        #pragma unroll
        for (int j = 0; j < 8; j++)
            #pragma unroll
            for (int c = 0; c < 6; c++) acc[j][c] = 0ULL;
        const float* ub = us + lane;
        const float* wb = sW + c0;
        #pragma unroll 2
        for (int k = 0; k < EDGE_DIM; k++) {
            const ulonglong2* wr = (const ulonglong2*)(wb + k * SWP);
            ulonglong2 w0 = wr[0], w1 = wr[1], w2 = wr[2];
            const float* ur = ub + k * ES_S;
            #pragma unroll
            for (int j = 0; j < 8; j++) {
                float uv = ur[32 * j];
                ull u2 = pk(uv, uv);
                acc[j][0] = fma2(u2, w0.x, acc[j][0]);
                acc[j][1] = fma2(u2, w0.y, acc[j][1]);
                acc[j][2] = fma2(u2, w1.x, acc[j][2]);
                acc[j][3] = fma2(u2, w1.y, acc[j][3]);
                acc[j][4] = fma2(u2, w2.x, acc[j][4]);
                acc[j][5] = fma2(u2, w2.y, acc[j][5]);
            }
        }
        #pragma unroll
        for (int j = 0; j < 8; j++) {
            float* ec = es + lane + 32 * j;
            #pragma unroll
            for (int c = 0; c < 6; c++) {
                float lo, hi; upk(acc[j][c], lo, hi);
                int ca = c0 + 2*c, cb = c0 + 2*c + 1;
                ec[ca * ES_S] = ec[ca * ES_S] + lo + sb2[ca];
                ec[cb * ES_S] = ec[cb * ES_S] + hi + sb2[cb];
            }
        }
    }
    __syncthreads();

    // ---- P5: per-edge LayerNorm of es (thread = edge) ----
    {
        float* ec = es + tid;
        float sum = 0.0f, sq = 0.0f;
        #pragma unroll 4
        for (int c = 0; c < EDGE_DIM; c++) {
            float v = ec[c * ES_S];
            sum += v; sq += v * v;
        }
        float mean = sum * (1.0f / EDGE_DIM);
        float var  = fmaxf(sq * (1.0f / EDGE_DIM) - mean * mean, 0.0f);
        float rstd = rsqrtf(var + LN_EPS);
        #pragma unroll 4
        for (int c = 0; c < EDGE_DIM; c++) {
            float v = ec[c * ES_S];
            ec[c * ES_S] = (v - mean) * rstd * sg[c] + sbt[c];
        }
    }
    __syncthreads();

    // ---- P6a: v = gelu(Qs[s] + Qd[d] + e @ Wv1 + b1) -> us rows 0..23 ----
    // group g = tid>>6 owns cols [6g, 6g+6); thread owns 4 edges t4+64j
    {
        int g = tid >> 6;
        int t4 = tid & 63;
        int c0 = 6 * g;
        ull acc[4][3];
        #pragma unroll
        for (int j = 0; j < 4; j++)
            #pragma unroll
            for (int c = 0; c < 3; c++) acc[j][c] = 0ULL;
        const float* eb = es + t4;
        const float* wb = sWv1 + c0;
        #pragma unroll 2
        for (int k = 0; k < EDGE_DIM; k++) {
            const ull* wr = (const ull*)(wb + k * WV1P);
            ull w0 = wr[0], w1 = wr[1], w2 = wr[2];
            const float* er = eb + k * ES_S;
            #pragma unroll
            for (int j = 0; j < 4; j++) {
                float ev = er[64 * j];
                ull e2 = pk(ev, ev);
                acc[j][0] = fma2(e2, w0, acc[j][0]);
                acc[j][1] = fma2(e2, w1, acc[j][1]);
                acc[j][2] = fma2(e2, w2, acc[j][2]);
            }
        }
        #pragma unroll
        for (int j = 0; j < 4; j++) {
            int ed = base + t4 + 64 * j;
            int s = src[ed], d = dst[ed];
            const float* qs = g_Qs + (size_t)s * HIDDEN + c0;
            const float* qd = g_Qd + (size_t)d * HIDDEN + c0;
            float2 qa0 = *(const float2*)(qs);
            float2 qa1 = *(const float2*)(qs + 2);
            float2 qa2 = *(const float2*)(qs + 4);
            float2 qb0 = *(const float2*)(qd);
            float2 qb1 = *(const float2*)(qd + 2);
            float2 qb2 = *(const float2*)(qd + 4);
            float add[6] = { qa0.x+qb0.x, qa0.y+qb0.y, qa1.x+qb1.x,
                             qa1.y+qb1.y, qa2.x+qb2.x, qa2.y+qb2.y };
            float* uc = us + t4 + 64 * j;
            #pragma unroll
            for (int c = 0; c < 3; c++) {
                float lo, hi; upk(acc[j][c], lo, hi);
                uc[(c0 + 2*c)     * ES_S] = gelu(lo + add[2*c]   + svb1[c0 + 2*c]);
                uc[(c0 + 2*c + 1) * ES_S] = gelu(hi + add[2*c+1] + svb1[c0 + 2*c + 1]);
            }
        }
    }
    __syncthreads();

    // ---- P6b: m = v @ Wv2 + b2 ; scatter-add into g_agg[dst] ----
    {
        int g = tid >> 6;
        int t4 = tid & 63;
        int c0 = 6 * g;
        ull acc[4][3];
        #pragma unroll
        for (int j = 0; j < 4; j++)
            #pragma unroll
            for (int c = 0; c < 3; c++) acc[j][c] = 0ULL;
        const float* ub = us + t4;
        const float* wb = sWv2 + c0;
        #pragma unroll 4
        for (int k = 0; k < HIDDEN; k++) {
            const ull* wr = (const ull*)(wb + k * HIDDEN);
            ull w0 = wr[0], w1 = wr[1], w2 = wr[2];
            const float* ur = ub + k * ES_S;
            #pragma unroll
            for (int j = 0; j < 4; j++) {
                float vv = ur[64 * j];
                ull v2 = pk(vv, vv);
                acc[j][0] = fma2(v2, w0, acc[j][0]);
                acc[j][1] = fma2(v2, w1, acc[j][1]);
                acc[j][2] = fma2(v2, w2, acc[j][2]);
            }
        }
        #pragma unroll
        for (int j = 0; j < 4; j++) {
            int ed = base + t4 + 64 * j;
            int d = dst[ed];
            float* ag = g_agg + (size_t)d * HIDDEN + c0;
            #pragma unroll
            for (int c = 0; c < 3; c++) {
                float lo, hi; upk(acc[j][c], lo, hi);
                atomicAdd(ag + 2*c,     lo + svb2[c0 + 2*c]);
                atomicAdd(ag + 2*c + 1, hi + svb2[c0 + 2*c + 1]);
            }
        }
    }

    // ---- P7: write updated e tile back (skipped on the last layer) ----
    if (store_e) {
        __syncthreads();
        for (int i = tid; i < EDGE_DIM * TE; i += ETHREADS) {
            int ee = i / EDGE_DIM, k = i - ee * EDGE_DIM;
            g_e[(size_t)(base + ee) * EDGE_DIM + k] = es[k * ES_S + ee];
        }
    }
}

// ---------------- node update: h = LN(h + agg / count) ----------------
__global__ void k_nodeup(const float* __restrict__ nvg, const float* __restrict__ nvb) {
    int n = blockIdx.x * blockDim.x + threadIdx.x;
    if (n >= N_NODES) return;
    float inv = 1.0f / fmaxf(g_cnt[n], 1.0f);
    float r[HIDDEN];
    float sum = 0.0f, sq = 0.0f;
    #pragma unroll
    for (int k = 0; k < HIDDEN; k += 4) {
        float4 hv = *(const float4*)(g_h + (size_t)n * HIDDEN + k);
        float4 av = *(const float4*)(g_agg + (size_t)n * HIDDEN + k);
        r[k]   = hv.x + av.x * inv; r[k+1] = hv.y + av.y * inv;
        r[k+2] = hv.z + av.z * inv; r[k+3] = hv.w + av.w * inv;
        sum += r[k] + r[k+1] + r[k+2] + r[k+3];
        sq  += r[k]*r[k] + r[k+1]*r[k+1] + r[k+2]*r[k+2] + r[k+3]*r[k+3];
    }
    float mean = sum * (1.0f / HIDDEN);
    float var  = fmaxf(sq * (1.0f / HIDDEN) - mean * mean, 0.0f);
    float rstd = rsqrtf(var + LN_EPS);
    #pragma unroll
    for (int k = 0; k < HIDDEN; k++) r[k] = (r[k] - mean) * rstd * nvg[k] + nvb[k];
    #pragma unroll
    for (int k = 0; k < HIDDEN; k += 4)
        *(float4*)(g_h + (size_t)n * HIDDEN + k) = make_float4(r[k], r[k+1], r[k+2], r[k+3]);
}

// ---------------- context head + final output ----------------
__global__ void __launch_bounds__(256) k_out(
    const float* __restrict__ ch_w1, const float* __restrict__ ch_b1,
    const float* __restrict__ ch_w2, const float* __restrict__ ch_b2,
    const float* __restrict__ mu, float* __restrict__ out)
{
    __shared__ float sw1[HIDDEN * HEAD_HIDDEN];
    __shared__ float sb1h[HEAD_HIDDEN];
    __shared__ float sw2[HEAD_HIDDEN];
    __shared__ float sb2h, smu;
    int tid = threadIdx.x;
    for (int i = tid; i < HIDDEN * HEAD_HIDDEN; i += 256) sw1[i] = ch_w1[i];
    if (tid < HEAD_HIDDEN) { sb1h[tid] = ch_b1[tid]; sw2[tid] = ch_w2[tid]; }
    if (tid == 0) { sb2h = ch_b2[0]; smu = mu[0]; }
    __syncthreads();
    int n = blockIdx.x * 256 + tid;
    if (n >= N_NODES) return;

    float h[HIDDEN];
    #pragma unroll
    for (int k = 0; k < HIDDEN; k += 4) {
        float4 v = *(const float4*)(g_h + (size_t)n * HIDDEN + k);
        h[k] = v.x; h[k+1] = v.y; h[k+2] = v.z; h[k+3] = v.w;
    }
    ull t[HEAD_HIDDEN / 2];
    #pragma unroll
    for (int j = 0; j < HEAD_HIDDEN / 2; j++) t[j] = pk(sb1h[2*j], sb1h[2*j+1]);
    #pragma unroll 4
    for (int k = 0; k < HIDDEN; k++) {
        ull hv = pk(h[k], h[k]);
        const ull* wr = (const ull*)(sw1 + k * HEAD_HIDDEN);
        #pragma unroll
        for (int j = 0; j < HEAD_HIDDEN / 2; j++) t[j] = fma2(hv, wr[j], t[j]);
    }
    float r = sb2h;
    #pragma unroll
    for (int j = 0; j < HEAD_HIDDEN / 2; j++) {
        float lo, hi; upk(t[j], lo, hi);
        r += gelu(lo) * sw2[2*j] + gelu(hi) * sw2[2*j+1];
    }
    out[n] = smu + g_intr[n] + r;
}

// ---------------- launch ----------------
extern "C" void kernel_launch(void* const* d_in, const int* in_sizes, int n_in,
                              void* d_out, int out_size) {
    (void)in_sizes; (void)n_in; (void)out_size;
    const float* x         = (const float*)d_in[0];
    const float* edge_attr = (const float*)d_in[1];
    const float* node_w    = (const float*)d_in[2];
    const float* node_b    = (const float*)d_in[3];
    const float* ih_w1     = (const float*)d_in[4];
    const float* ih_b1     = (const float*)d_in[5];
    const float* ih_w2     = (const float*)d_in[6];
    const float* ih_b2     = (const float*)d_in[7];
    const float* pe_w1     = (const float*)d_in[8];
    const float* pe_b1     = (const float*)d_in[9];
    const float* pe_w2     = (const float*)d_in[10];
    const float* pe_b2     = (const float*)d_in[11];
    const float* pv_w1     = (const float*)d_in[12];
    const float* pv_b1     = (const float*)d_in[13];
    const float* pv_w2     = (const float*)d_in[14];
    const float* pv_b2     = (const float*)d_in[15];
    const float* ne_g      = (const float*)d_in[16];
    const float* ne_b      = (const float*)d_in[17];
    const float* nv_g      = (const float*)d_in[18];
    const float* nv_b      = (const float*)d_in[19];
    const float* ch_w1     = (const float*)d_in[20];
    const float* ch_b1     = (const float*)d_in[21];
    const float* ch_w2     = (const float*)d_in[22];
    const float* ch_b2     = (const float*)d_in[23];
    const float* mu        = (const float*)d_in[24];
    const int*   eidx      = (const int*)d_in[25];
    const int* src = eidx;
    const int* dst = eidx + N_EDGES;
    float* out = (float*)d_out;

    cudaFuncSetAttribute(k_edge, cudaFuncAttributeMaxDynamicSharedMemorySize, EDGE_SMEM_BYTES);

    const int NB_N = (N_NODES + 255) / 256;
    const int NB_E = N_EDGES / 256;          // 3125, exact
    const int NB_A = (N_NODES * HIDDEN + 255) / 256;

    k_input<<<NB_N, 256>>>(x, node_w, node_b, ih_w1, ih_b1, ih_w2, ih_b2);
    k_zero_cnt<<<NB_N, 256>>>();
    k_count<<<NB_E, 256>>>(dst);

    for (int i = 0; i < DEPTH; i++) {
        const float* pe1 = pe_w1 + (size_t)i * 132 * EDGE_DIM;
        const float* pv1 = pv_w1 + (size_t)i * 132 * HIDDEN;
        k_zero_agg<<<NB_A, 256>>>();
        k_nodeproj<<<NB_N, 256>>>(pe1, pv1);
        k_edge<<<NB_E, ETHREADS, EDGE_SMEM_BYTES>>>(
            (i == 0) ? edge_attr : (const float*)nullptr,
            src, dst,
            pe1 + 48 * EDGE_DIM,                 // We1: rows 48..131 of pe_w1[i]
            pe_b1 + (size_t)i * EDGE_DIM,
            pe_w2 + (size_t)i * EDGE_DIM * EDGE_DIM,
            pe_b2 + (size_t)i * EDGE_DIM,
            ne_g + (size_t)i * EDGE_DIM,
            ne_b + (size_t)i * EDGE_DIM,
            pv1 + 48 * HIDDEN,                   // Wv1: rows 48..131 of pv_w1[i]
            pv_b1 + (size_t)i * HIDDEN,
            pv_w2 + (size_t)i * HIDDEN * HIDDEN,
            pv_b2 + (size_t)i * HIDDEN,
            (i + 1 < DEPTH) ? 1 : 0);
        k_nodeup<<<NB_N, 256>>>(nv_g + (size_t)i * HIDDEN, nv_b + (size_t)i * HIDDEN);
    }

    k_out<<<NB_N, 256>>>(ch_w1, ch_b1, ch_w2, ch_b2, mu, out);
}

// round 16
// speedup vs baseline: 1.1706x; 1.0070x over previous
#include <cuda_runtime.h>
#include <cuda_bf16.h>
#include <math.h>

#define N_NODES   100000
#define N_EDGES   800000
#define NODE_IN   32
#define EDGE_DIM  84
#define HIDDEN    24
#define HEAD_HIDDEN 20
#define DEPTH     2
#define LN_EPS    1e-5f

#define TE 256            // edges per block
#define ETHREADS 512
#define ES_S (TE + 1)     // 257: stride ≡ 1 mod 32 -> conflict-free everywhere

typedef unsigned long long ull;

// ---------------- packed f32x2 helpers (Blackwell FFMA2) ----------------
__device__ __forceinline__ ull pk(float lo, float hi) {
    ull r; asm("mov.b64 %0, {%1,%2};" : "=l"(r) : "f"(lo), "f"(hi)); return r;
}
__device__ __forceinline__ void upk(ull v, float& lo, float& hi) {
    asm("mov.b64 {%0,%1}, %2;" : "=f"(lo), "=f"(hi) : "l"(v));
}
__device__ __forceinline__ ull fma2(ull a, ull b, ull c) {
    ull d; asm("fma.rn.f32x2 %0, %1, %2, %3;" : "=l"(d) : "l"(a), "l"(b), "l"(c)); return d;
}
__device__ __forceinline__ float gelu(float x) {
    return 0.5f * x * (1.0f + erff(x * 0.7071067811865476f));
}

// ---------------- scratch (device globals: allocation-free) ----------------
__device__ float g_h[N_NODES * HIDDEN];
__device__ float g_intr[N_NODES];
__device__ float g_cnt[N_NODES];
__device__ float g_Ps[N_NODES * EDGE_DIM];
__device__ float g_Pd[N_NODES * EDGE_DIM];
__device__ float g_Qs[N_NODES * HIDDEN];
__device__ float g_Qd[N_NODES * HIDDEN];
__device__ float g_agg[N_NODES * HIDDEN];
__device__ float g_e[(size_t)N_EDGES * EDGE_DIM];

// ---------------- edge-count kernel ----------------
__global__ void k_count(const int* __restrict__ dst) {
    int e = blockIdx.x * blockDim.x + threadIdx.x;
    if (e < N_EDGES) atomicAdd(&g_cnt[dst[e]], 1.0f);
}

// ---------------- input projection + intrinsic head (+ cnt zeroing) ----------------
__global__ void __launch_bounds__(256) k_input(
    const float* __restrict__ x, const float* __restrict__ node_w,
    const float* __restrict__ node_b, const float* __restrict__ ih_w1,
    const float* __restrict__ ih_b1, const float* __restrict__ ih_w2,
    const float* __restrict__ ih_b2)
{
    __shared__ float sw[NODE_IN * HIDDEN];
    __shared__ float sbias[HIDDEN];
    __shared__ float sw1[HIDDEN * HEAD_HIDDEN];
    __shared__ float sb1h[HEAD_HIDDEN];
    __shared__ float sw2[HEAD_HIDDEN];
    __shared__ float sb2h;
    int tid = threadIdx.x;
    for (int i = tid; i < NODE_IN * HIDDEN; i += 256) sw[i] = node_w[i];
    for (int i = tid; i < HIDDEN * HEAD_HIDDEN; i += 256) sw1[i] = ih_w1[i];
    if (tid < HIDDEN) sbias[tid] = node_b[tid];
    if (tid < HEAD_HIDDEN) { sb1h[tid] = ih_b1[tid]; sw2[tid] = ih_w2[tid]; }
    if (tid == 0) sb2h = ih_b2[0];
    __syncthreads();
    int n = blockIdx.x * 256 + tid;
    if (n >= N_NODES) return;
    g_cnt[n] = 0.0f;

    float xr[NODE_IN];
    #pragma unroll
    for (int k = 0; k < NODE_IN; k += 4) {
        float4 v = *(const float4*)(x + (size_t)n * NODE_IN + k);
        xr[k] = v.x; xr[k+1] = v.y; xr[k+2] = v.z; xr[k+3] = v.w;
    }
    ull acc[HIDDEN / 2];
    #pragma unroll
    for (int j = 0; j < HIDDEN / 2; j++) acc[j] = pk(sbias[2*j], sbias[2*j+1]);
    #pragma unroll 4
    for (int k = 0; k < NODE_IN; k++) {
        ull xv = pk(xr[k], xr[k]);
        const ulonglong2* wr = (const ulonglong2*)(sw + k * HIDDEN);
        ulonglong2 w0 = wr[0], w1 = wr[1], w2 = wr[2], w3 = wr[3], w4 = wr[4], w5 = wr[5];
        acc[0]=fma2(xv,w0.x,acc[0]);  acc[1]=fma2(xv,w0.y,acc[1]);
        acc[2]=fma2(xv,w1.x,acc[2]);  acc[3]=fma2(xv,w1.y,acc[3]);
        acc[4]=fma2(xv,w2.x,acc[4]);  acc[5]=fma2(xv,w2.y,acc[5]);
        acc[6]=fma2(xv,w3.x,acc[6]);  acc[7]=fma2(xv,w3.y,acc[7]);
        acc[8]=fma2(xv,w4.x,acc[8]);  acc[9]=fma2(xv,w4.y,acc[9]);
        acc[10]=fma2(xv,w5.x,acc[10]); acc[11]=fma2(xv,w5.y,acc[11]);
    }
    float h[HIDDEN];
    #pragma unroll
    for (int j = 0; j < HIDDEN / 2; j++) upk(acc[j], h[2*j], h[2*j+1]);
    #pragma unroll
    for (int k = 0; k < HIDDEN; k += 4)
        *(float4*)(g_h + (size_t)n * HIDDEN + k) = make_float4(h[k], h[k+1], h[k+2], h[k+3]);

    ull t[HEAD_HIDDEN / 2];
    #pragma unroll
    for (int j = 0; j < HEAD_HIDDEN / 2; j++) t[j] = pk(sb1h[2*j], sb1h[2*j+1]);
    #pragma unroll 4
    for (int k = 0; k < HIDDEN; k++) {
        ull hv = pk(h[k], h[k]);
        const ull* wr = (const ull*)(sw1 + k * HEAD_HIDDEN);
        #pragma unroll
        for (int j = 0; j < HEAD_HIDDEN / 2; j++) t[j] = fma2(hv, wr[j], t[j]);
    }
    float r = sb2h;
    #pragma unroll
    for (int j = 0; j < HEAD_HIDDEN / 2; j++) {
        float lo, hi; upk(t[j], lo, hi);
        r += gelu(lo) * sw2[2*j] + gelu(hi) * sw2[2*j+1];
    }
    g_intr[n] = r;
}

// ---------------- per-layer node-side projections (+ agg zeroing) ----------------
__global__ void __launch_bounds__(256) k_nodeproj(
    const float* __restrict__ pe_w1_l, const float* __restrict__ pv_w1_l)
{
    __shared__ float we[48 * 88];
    __shared__ float wv[48 * HIDDEN];
    int tid = threadIdx.x;
    for (int i = tid; i < 48 * EDGE_DIM; i += 256) {
        int k = i / EDGE_DIM, c = i - k * EDGE_DIM;
        we[k * 88 + c] = pe_w1_l[i];
    }
    for (int i = tid; i < 48 * HIDDEN; i += 256) wv[i] = pv_w1_l[i];
    __syncthreads();
    int n = blockIdx.x * 256 + tid;
    if (n >= N_NODES) return;

    // zero g_agg for this node (before the edge kernel's atomics)
    float4 z = make_float4(0.f, 0.f, 0.f, 0.f);
    #pragma unroll
    for (int k = 0; k < HIDDEN; k += 4) *(float4*)(g_agg + (size_t)n * HIDDEN + k) = z;

    ull h2[HIDDEN];
    #pragma unroll
    for (int k = 0; k < HIDDEN; k += 4) {
        float4 v = *(const float4*)(g_h + (size_t)n * HIDDEN + k);
        h2[k] = pk(v.x, v.x); h2[k+1] = pk(v.y, v.y);
        h2[k+2] = pk(v.z, v.z); h2[k+3] = pk(v.w, v.w);
    }
    #pragma unroll 1
    for (int ch = 0; ch < 7; ch++) {
        int c0 = ch * 12;
        ull as[6], ad[6];
        #pragma unroll
        for (int j = 0; j < 6; j++) { as[j] = 0ULL; ad[j] = 0ULL; }
        #pragma unroll 4
        for (int k = 0; k < 24; k++) {
            const ulonglong2* ws = (const ulonglong2*)(we + k * 88 + c0);
            const ulonglong2* wd = (const ulonglong2*)(we + (k + 24) * 88 + c0);
            ulonglong2 s0 = ws[0], s1 = ws[1], s2 = ws[2];
            ulonglong2 d0 = wd[0], d1 = wd[1], d2 = wd[2];
            ull hk = h2[k];
            as[0]=fma2(hk,s0.x,as[0]); as[1]=fma2(hk,s0.y,as[1]);
            as[2]=fma2(hk,s1.x,as[2]); as[3]=fma2(hk,s1.y,as[3]);
            as[4]=fma2(hk,s2.x,as[4]); as[5]=fma2(hk,s2.y,as[5]);
            ad[0]=fma2(hk,d0.x,ad[0]); ad[1]=fma2(hk,d0.y,ad[1]);
            ad[2]=fma2(hk,d1.x,ad[2]); ad[3]=fma2(hk,d1.y,ad[3]);
            ad[4]=fma2(hk,d2.x,ad[4]); ad[5]=fma2(hk,d2.y,ad[5]);
        }
        float o[12];
        #pragma unroll
        for (int j = 0; j < 6; j++) upk(as[j], o[2*j], o[2*j+1]);
        #pragma unroll
        for (int k = 0; k < 12; k += 4)
            *(float4*)(g_Ps + (size_t)n * EDGE_DIM + c0 + k) = make_float4(o[k], o[k+1], o[k+2], o[k+3]);
        #pragma unroll
        for (int j = 0; j < 6; j++) upk(ad[j], o[2*j], o[2*j+1]);
        #pragma unroll
        for (int k = 0; k < 12; k += 4)
            *(float4*)(g_Pd + (size_t)n * EDGE_DIM + c0 + k) = make_float4(o[k], o[k+1], o[k+2], o[k+3]);
    }
    #pragma unroll 1
    for (int ch = 0; ch < 2; ch++) {
        int c0 = ch * 12;
        ull as[6], ad[6];
        #pragma unroll
        for (int j = 0; j < 6; j++) { as[j] = 0ULL; ad[j] = 0ULL; }
        #pragma unroll 4
        for (int k = 0; k < 24; k++) {
            const ulonglong2* ws = (const ulonglong2*)(wv + k * HIDDEN + c0);
            const ulonglong2* wd = (const ulonglong2*)(wv + (k + 24) * HIDDEN + c0);
            ulonglong2 s0 = ws[0], s1 = ws[1], s2 = ws[2];
            ulonglong2 d0 = wd[0], d1 = wd[1], d2 = wd[2];
            ull hk = h2[k];
            as[0]=fma2(hk,s0.x,as[0]); as[1]=fma2(hk,s0.y,as[1]);
            as[2]=fma2(hk,s1.x,as[2]); as[3]=fma2(hk,s1.y,as[3]);
            as[4]=fma2(hk,s2.x,as[4]); as[5]=fma2(hk,s2.y,as[5]);
            ad[0]=fma2(hk,d0.x,ad[0]); ad[1]=fma2(hk,d0.y,ad[1]);
            ad[2]=fma2(hk,d1.x,ad[2]); ad[3]=fma2(hk,d1.y,ad[3]);
            ad[4]=fma2(hk,d2.x,ad[4]); ad[5]=fma2(hk,d2.y,ad[5]);
        }
        float o[12];
        #pragma unroll
        for (int j = 0; j < 6; j++) upk(as[j], o[2*j], o[2*j+1]);
        #pragma unroll
        for (int k = 0; k < 12; k += 4)
            *(float4*)(g_Qs + (size_t)n * HIDDEN + c0 + k) = make_float4(o[k], o[k+1], o[k+2], o[k+3]);
        #pragma unroll
        for (int j = 0; j < 6; j++) upk(ad[j], o[2*j], o[2*j+1]);
        #pragma unroll
        for (int k = 0; k < 12; k += 4)
            *(float4*)(g_Qd + (size_t)n * HIDDEN + c0 + k) = make_float4(o[k], o[k+1], o[k+2], o[k+3]);
    }
}

// ---------------- fused per-layer edge kernel (512 threads, 14x6-col GEMM warps) ----------------
// SMEM (floats): es[84][257] + us[84][257] + sW[84][84] + sWv1[84][24] + sWv2[24][24]
//                + biases(384) + pad(24) + sidx(256) + didx(256) = 53744 floats = 215.0 KB
#define EDGE_SMEM_FLOATS (2 * EDGE_DIM * ES_S + EDGE_DIM * EDGE_DIM + EDGE_DIM * HIDDEN + HIDDEN * HIDDEN + 384 + 24 + 2 * TE)
#define EDGE_SMEM_BYTES  (EDGE_SMEM_FLOATS * 4)

__global__ void __launch_bounds__(ETHREADS, 1) k_edge(
    const float* __restrict__ ein_p,
    const int* __restrict__ src, const int* __restrict__ dst,
    const float* __restrict__ we1,  const float* __restrict__ pb1,
    const float* __restrict__ we2,  const float* __restrict__ pb2,
    const float* __restrict__ neg,  const float* __restrict__ neb,
    const float* __restrict__ wv1,  const float* __restrict__ vb1,
    const float* __restrict__ wv2,  const float* __restrict__ vb2,
    int store_e)
{
    extern __shared__ float smem[];
    float* es   = smem;
    float* us   = es + EDGE_DIM * ES_S;
    float* sW   = us + EDGE_DIM * ES_S;                 // 84x84, reused We1 -> pe_w2
    float* sWv1 = sW + EDGE_DIM * EDGE_DIM;             // 84x24
    float* sWv2 = sWv1 + EDGE_DIM * HIDDEN;             // 24x24
    float* sb1  = sWv2 + HIDDEN * HIDDEN;               // 84
    float* sb2  = sb1 + EDGE_DIM;                       // 84
    float* sg   = sb2 + EDGE_DIM;                       // 84
    float* sbt  = sg + EDGE_DIM;                        // 84
    float* svb1 = sbt + EDGE_DIM;                       // 24
    float* svb2 = svb1 + HIDDEN;                        // 24 (+24 pad before sidx)
    int*   sidx = (int*)(svb2 + 2 * HIDDEN);            // 256
    int*   didx = sidx + TE;                            // 256

    int tid = threadIdx.x;
    int base = blockIdx.x * TE;
    const float* ein = ein_p ? ein_p : g_e;

    // ---- P1: stage e tile (transposed), weights, params, indices ----
    for (int i = tid; i < EDGE_DIM * TE; i += ETHREADS) {
        int ee = i / EDGE_DIM, k = i - ee * EDGE_DIM;
        es[k * ES_S + ee] = ein[(size_t)(base + ee) * EDGE_DIM + k];
    }
    for (int i = tid; i < EDGE_DIM * EDGE_DIM; i += ETHREADS) sW[i] = we1[i];
    for (int i = tid; i < EDGE_DIM * HIDDEN; i += ETHREADS) sWv1[i] = wv1[i];
    for (int i = tid; i < HIDDEN * HIDDEN; i += ETHREADS) sWv2[i] = wv2[i];
    if (tid < EDGE_DIM) { sb1[tid] = pb1[tid]; sb2[tid] = pb2[tid]; sg[tid] = neg[tid]; sbt[tid] = neb[tid]; }
    if (tid >= 128 && tid < 128 + HIDDEN) { svb1[tid-128] = vb1[tid-128]; svb2[tid-128] = vb2[tid-128]; }
    if (tid >= 256) { sidx[tid-256] = src[base + tid - 256]; didx[tid-256] = dst[base + tid - 256]; }
    __syncthreads();

    int wid = tid >> 5, lane = tid & 31;

    // ---- P2: u = gelu(Ps[s] + Pd[d] + e @ We1 + b1) ----
    // warp w (0..13) owns cols [6w, 6w+6); thread owns 8 edges lane+32j
    if (wid < 14) {
        int c0 = wid * 6;
        ull acc[8][3];
        #pragma unroll
        for (int j = 0; j < 8; j++)
            #pragma unroll
            for (int c = 0; c < 3; c++) acc[j][c] = 0ULL;
        const float* eb = es + lane;
        const float* wb = sW + c0;
        #pragma unroll 2
        for (int k = 0; k < EDGE_DIM; k++) {
            const ull* wr = (const ull*)(wb + k * EDGE_DIM);
            ull w0 = wr[0], w1 = wr[1], w2 = wr[2];
            const float* er = eb + k * ES_S;
            #pragma unroll
            for (int j = 0; j < 8; j++) {
                float ev = er[32 * j];
                ull e2 = pk(ev, ev);
                acc[j][0] = fma2(e2, w0, acc[j][0]);
                acc[j][1] = fma2(e2, w1, acc[j][1]);
                acc[j][2] = fma2(e2, w2, acc[j][2]);
            }
        }
        #pragma unroll
        for (int j = 0; j < 8; j++) {
            int ee = lane + 32 * j;
            int s = sidx[ee], d = didx[ee];
            const float* ps = g_Ps + (size_t)s * EDGE_DIM + c0;
            const float* pd = g_Pd + (size_t)d * EDGE_DIM + c0;
            float2 a0 = *(const float2*)(ps);
            float2 a1 = *(const float2*)(ps + 2);
            float2 a2 = *(const float2*)(ps + 4);
            float2 b0 = *(const float2*)(pd);
            float2 b1 = *(const float2*)(pd + 2);
            float2 b2 = *(const float2*)(pd + 4);
            float add[6] = { a0.x+b0.x, a0.y+b0.y, a1.x+b1.x,
                             a1.y+b1.y, a2.x+b2.x, a2.y+b2.y };
            float* uc = us + ee;
            #pragma unroll
            for (int c = 0; c < 3; c++) {
                float lo, hi; upk(acc[j][c], lo, hi);
                uc[(c0 + 2*c)     * ES_S] = gelu(lo + add[2*c]   + sb1[c0 + 2*c]);
                uc[(c0 + 2*c + 1) * ES_S] = gelu(hi + add[2*c+1] + sb1[c0 + 2*c + 1]);
            }
        }
    }
    __syncthreads();

    // ---- P3: reload sW with pe_w2 ----
    for (int i = tid; i < EDGE_DIM * EDGE_DIM; i += ETHREADS) sW[i] = we2[i];
    __syncthreads();

    // ---- P4: r = e + (u @ pe_w2 + b2)  -> es ----
    if (wid < 14) {
        int c0 = wid * 6;
        ull acc[8][3];
        #pragma unroll
        for (int j = 0; j < 8; j++)
            #pragma unroll
            for (int c = 0; c < 3; c++) acc[j][c] = 0ULL;
        const float* ub = us + lane;
        const float* wb = sW + c0;
        #pragma unroll 2
        for (int k = 0; k < EDGE_DIM; k++) {
            const ull* wr = (const ull*)(wb + k * EDGE_DIM);
            ull w0 = wr[0], w1 = wr[1], w2 = wr[2];
            const float* ur = ub + k * ES_S;
            #pragma unroll
            for (int j = 0; j < 8; j++) {
                float uv = ur[32 * j];
                ull u2 = pk(uv, uv);
                acc[j][0] = fma2(u2, w0, acc[j][0]);
                acc[j][1] = fma2(u2, w1, acc[j][1]);
                acc[j][2] = fma2(u2, w2, acc[j][2]);
            }
        }
        #pragma unroll
        for (int j = 0; j < 8; j++) {
            float* ec = es + lane + 32 * j;
            #pragma unroll
            for (int c = 0; c < 3; c++) {
                float lo, hi; upk(acc[j][c], lo, hi);
                int ca = c0 + 2*c, cb = ca + 1;
                ec[ca * ES_S] = ec[ca * ES_S] + lo + sb2[ca];
                ec[cb * ES_S] = ec[cb * ES_S] + hi + sb2[cb];
            }
        }
    }
    __syncthreads();

    // ---- P5: per-edge LayerNorm of es (threads 0..255) ----
    if (tid < TE) {
        float* ec = es + tid;
        float sum = 0.0f, sq = 0.0f;
        #pragma unroll 4
        for (int c = 0; c < EDGE_DIM; c++) {
            float v = ec[c * ES_S];
            sum += v; sq += v * v;
        }
        float mean = sum * (1.0f / EDGE_DIM);
        float var  = fmaxf(sq * (1.0f / EDGE_DIM) - mean * mean, 0.0f);
        float rstd = rsqrtf(var + LN_EPS);
        #pragma unroll 4
        for (int c = 0; c < EDGE_DIM; c++) {
            float v = ec[c * ES_S];
            ec[c * ES_S] = (v - mean) * rstd * sg[c] + sbt[c];
        }
    }
    __syncthreads();

    // ---- P6a: v = gelu(Qs[s] + Qd[d] + e @ Wv1 + b1) -> us rows 0..23 ----
    // group g = tid>>7 (0..3) owns cols [6g,6g+6); thread owns 2 edges t2+128j
    {
        int g = tid >> 7;
        int t2 = tid & 127;
        int c0 = 6 * g;
        ull acc[2][3];
        #pragma unroll
        for (int j = 0; j < 2; j++)
            #pragma unroll
            for (int c = 0; c < 3; c++) acc[j][c] = 0ULL;
        const float* eb = es + t2;
        const float* wb = sWv1 + c0;
        #pragma unroll 2
        for (int k = 0; k < EDGE_DIM; k++) {
            const ull* wr = (const ull*)(wb + k * HIDDEN);
            ull w0 = wr[0], w1 = wr[1], w2 = wr[2];
            const float* er = eb + k * ES_S;
            #pragma unroll
            for (int j = 0; j < 2; j++) {
                float ev = er[128 * j];
                ull e2 = pk(ev, ev);
                acc[j][0] = fma2(e2, w0, acc[j][0]);
                acc[j][1] = fma2(e2, w1, acc[j][1]);
                acc[j][2] = fma2(e2, w2, acc[j][2]);
            }
        }
        #pragma unroll
        for (int j = 0; j < 2; j++) {
            int ee = t2 + 128 * j;
            int s = sidx[ee], d = didx[ee];
            const float* qs = g_Qs + (size_t)s * HIDDEN + c0;
            const float* qd = g_Qd + (size_t)d * HIDDEN + c0;
            float2 a0 = *(const float2*)(qs);
            float2 a1 = *(const float2*)(qs + 2);
            float2 a2 = *(const float2*)(qs + 4);
            float2 b0 = *(const float2*)(qd);
            float2 b1 = *(const float2*)(qd + 2);
            float2 b2 = *(const float2*)(qd + 4);
            float add[6] = { a0.x+b0.x, a0.y+b0.y, a1.x+b1.x,
                             a1.y+b1.y, a2.x+b2.x, a2.y+b2.y };
            float* uc = us + ee;
            #pragma unroll
            for (int c = 0; c < 3; c++) {
                float lo, hi; upk(acc[j][c], lo, hi);
                uc[(c0 + 2*c)     * ES_S] = gelu(lo + add[2*c]   + svb1[c0 + 2*c]);
                uc[(c0 + 2*c + 1) * ES_S] = gelu(hi + add[2*c+1] + svb1[c0 + 2*c + 1]);
            }
        }
    }
    __syncthreads();

    // ---- P6b: m = v @ Wv2 + b2 ; scatter-add into g_agg[dst] ----
    {
        int g = tid >> 7;
        int t2 = tid & 127;
        int c0 = 6 * g;
        ull acc[2][3];
        #pragma unroll
        for (int j = 0; j < 2; j++)
            #pragma unroll
            for (int c = 0; c < 3; c++) acc[j][c] = 0ULL;
        const float* ub = us + t2;
        const float* wb = sWv2 + c0;
        #pragma unroll 4
        for (int k = 0; k < HIDDEN; k++) {
            const ull* wr = (const ull*)(wb + k * HIDDEN);
            ull w0 = wr[0], w1 = wr[1], w2 = wr[2];
            const float* ur = ub + k * ES_S;
            #pragma unroll
            for (int j = 0; j < 2; j++) {
                float vv = ur[128 * j];
                ull v2 = pk(vv, vv);
                acc[j][0] = fma2(v2, w0, acc[j][0]);
                acc[j][1] = fma2(v2, w1, acc[j][1]);
                acc[j][2] = fma2(v2, w2, acc[j][2]);
            }
        }
        #pragma unroll
        for (int j = 0; j < 2; j++) {
            int ee = t2 + 128 * j;
            int d = didx[ee];
            float* ag = g_agg + (size_t)d * HIDDEN + c0;
            #pragma unroll
            for (int c = 0; c < 3; c++) {
                float lo, hi; upk(acc[j][c], lo, hi);
                atomicAdd(ag + 2*c,     lo + svb2[c0 + 2*c]);
                atomicAdd(ag + 2*c + 1, hi + svb2[c0 + 2*c + 1]);
            }
        }
    }

    // ---- P7: write updated e tile back (skipped on last layer) ----
    if (store_e) {
        __syncthreads();
        for (int i = tid; i < EDGE_DIM * TE; i += ETHREADS) {
            int ee = i / EDGE_DIM, k = i - ee * EDGE_DIM;
            g_e[(size_t)(base + ee) * EDGE_DIM + k] = es[k * ES_S + ee];
        }
    }
}

// ---------------- node update: h = LN(h + agg / count) ----------------
__global__ void k_nodeup(const float* __restrict__ nvg, const float* __restrict__ nvb) {
    int n = blockIdx.x * blockDim.x + threadIdx.x;
    if (n >= N_NODES) return;
    float inv = 1.0f / fmaxf(g_cnt[n], 1.0f);
    float r[HIDDEN];
    float sum = 0.0f, sq = 0.0f;
    #pragma unroll
    for (int k = 0; k < HIDDEN; k += 4) {
        float4 hv = *(const float4*)(g_h + (size_t)n * HIDDEN + k);
        float4 av = *(const float4*)(g_agg + (size_t)n * HIDDEN + k);
        r[k]   = hv.x + av.x * inv; r[k+1] = hv.y + av.y * inv;
        r[k+2] = hv.z + av.z * inv; r[k+3] = hv.w + av.w * inv;
        sum += r[k] + r[k+1] + r[k+2] + r[k+3];
        sq  += r[k]*r[k] + r[k+1]*r[k+1] + r[k+2]*r[k+2] + r[k+3]*r[k+3];
    }
    float mean = sum * (1.0f / HIDDEN);
    float var  = fmaxf(sq * (1.0f / HIDDEN) - mean * mean, 0.0f);
    float rstd = rsqrtf(var + LN_EPS);
    #pragma unroll
    for (int k = 0; k < HIDDEN; k++) r[k] = (r[k] - mean) * rstd * nvg[k] + nvb[k];
    #pragma unroll
    for (int k = 0; k < HIDDEN; k += 4)
        *(float4*)(g_h + (size_t)n * HIDDEN + k) = make_float4(r[k], r[k+1], r[k+2], r[k+3]);
}

// ---------------- context head + final output ----------------
__global__ void __launch_bounds__(256) k_out(
    const float* __restrict__ ch_w1, const float* __restrict__ ch_b1,
    const float* __restrict__ ch_w2, const float* __restrict__ ch_b2,
    const float* __restrict__ mu, float* __restrict__ out)
{
    __shared__ float sw1[HIDDEN * HEAD_HIDDEN];
    __shared__ float sb1h[HEAD_HIDDEN];
    __shared__ float sw2[HEAD_HIDDEN];
    __shared__ float sb2h, smu;
    int tid = threadIdx.x;
    for (int i = tid; i < HIDDEN * HEAD_HIDDEN; i += 256) sw1[i] = ch_w1[i];
    if (tid < HEAD_HIDDEN) { sb1h[tid] = ch_b1[tid]; sw2[tid] = ch_w2[tid]; }
    if (tid == 0) { sb2h = ch_b2[0]; smu = mu[0]; }
    __syncthreads();
    int n = blockIdx.x * 256 + tid;
    if (n >= N_NODES) return;

    float h[HIDDEN];
    #pragma unroll
    for (int k = 0; k < HIDDEN; k += 4) {
        float4 v = *(const float4*)(g_h + (size_t)n * HIDDEN + k);
        h[k] = v.x; h[k+1] = v.y; h[k+2] = v.z; h[k+3] = v.w;
    }
    ull t[HEAD_HIDDEN / 2];
    #pragma unroll
    for (int j = 0; j < HEAD_HIDDEN / 2; j++) t[j] = pk(sb1h[2*j], sb1h[2*j+1]);
    #pragma unroll 4
    for (int k = 0; k < HIDDEN; k++) {
        ull hv = pk(h[k], h[k]);
        const ull* wr = (const ull*)(sw1 + k * HEAD_HIDDEN);
        #pragma unroll
        for (int j = 0; j < HEAD_HIDDEN / 2; j++) t[j] = fma2(hv, wr[j], t[j]);
    }
    float r = sb2h;
    #pragma unroll
    for (int j = 0; j < HEAD_HIDDEN / 2; j++) {
        float lo, hi; upk(t[j], lo, hi);
        r += gelu(lo) * sw2[2*j] + gelu(hi) * sw2[2*j+1];
    }
    out[n] = smu + g_intr[n] + r;
}

// ---------------- launch ----------------
extern "C" void kernel_launch(void* const* d_in, const int* in_sizes, int n_in,
                              void* d_out, int out_size) {
    (void)in_sizes; (void)n_in; (void)out_size;
    const float* x         = (const float*)d_in[0];
    const float* edge_attr = (const float*)d_in[1];
    const float* node_w    = (const float*)d_in[2];
    const float* node_b    = (const float*)d_in[3];
    const float* ih_w1     = (const float*)d_in[4];
    const float* ih_b1     = (const float*)d_in[5];
    const float* ih_w2     = (const float*)d_in[6];
    const float* ih_b2     = (const float*)d_in[7];
    const float* pe_w1     = (const float*)d_in[8];
    const float* pe_b1     = (const float*)d_in[9];
    const float* pe_w2     = (const float*)d_in[10];
    const float* pe_b2     = (const float*)d_in[11];
    const float* pv_w1     = (const float*)d_in[12];
    const float* pv_b1     = (const float*)d_in[13];
    const float* pv_w2     = (const float*)d_in[14];
    const float* pv_b2     = (const float*)d_in[15];
    const float* ne_g      = (const float*)d_in[16];
    const float* ne_b      = (const float*)d_in[17];
    const float* nv_g      = (const float*)d_in[18];
    const float* nv_b      = (const float*)d_in[19];
    const float* ch_w1     = (const float*)d_in[20];
    const float* ch_b1     = (const float*)d_in[21];
    const float* ch_w2     = (const float*)d_in[22];
    const float* ch_b2     = (const float*)d_in[23];
    const float* mu        = (const float*)d_in[24];
    const int*   eidx      = (const int*)d_in[25];
    const int* src = eidx;
    const int* dst = eidx + N_EDGES;
    float* out = (float*)d_out;

    cudaFuncSetAttribute(k_edge, cudaFuncAttributeMaxDynamicSharedMemorySize, EDGE_SMEM_BYTES);

    const int NB_N = (N_NODES + 255) / 256;
    const int NB_E = N_EDGES / 256;          // 3125, exact

    k_input<<<NB_N, 256>>>(x, node_w, node_b, ih_w1, ih_b1, ih_w2, ih_b2);
    k_count<<<NB_E, 256>>>(dst);

    for (int i = 0; i < DEPTH; i++) {
        const float* pe1 = pe_w1 + (size_t)i * 132 * EDGE_DIM;
        const float* pv1 = pv_w1 + (size_t)i * 132 * HIDDEN;
        k_nodeproj<<<NB_N, 256>>>(pe1, pv1);
        k_edge<<<NB_E, ETHREADS, EDGE_SMEM_BYTES>>>(
            (i == 0) ? edge_attr : (const float*)nullptr,
            src, dst,
            pe1 + 48 * EDGE_DIM,                 // We1: rows 48..131 of pe_w1[i]
            pe_b1 + (size_t)i * EDGE_DIM,
            pe_w2 + (size_t)i * EDGE_DIM * EDGE_DIM,
            pe_b2 + (size_t)i * EDGE_DIM,
            ne_g + (size_t)i * EDGE_DIM,
            ne_b + (size_t)i * EDGE_DIM,
            pv1 + 48 * HIDDEN,                   // Wv1: rows 48..131 of pv_w1[i]
            pv_b1 + (size_t)i * HIDDEN,
            pv_w2 + (size_t)i * HIDDEN * HIDDEN,
            pv_b2 + (size_t)i * HIDDEN,
            (i + 1 < DEPTH) ? 1 : 0);
        k_nodeup<<<NB_N, 256>>>(nv_g + (size_t)i * HIDDEN, nv_b + (size_t)i * HIDDEN);
    }

    k_out<<<NB_N, 256>>>(ch_w1, ch_b1, ch_w2, ch_b2, mu, out);
}